// round 11
// baseline (speedup 1.0000x reference)
#include <cuda_runtime.h>
#include <cstdint>

#define NVEC     131072
#define DDIM     128
#define KCODES   1024
#define BN       64          // vectors per block
#define BKC      128         // codes per chunk
#define NCHUNK   (KCODES / BKC)
#define NT       512

// dynamic smem (floats)
#define F_ZS2   0                        // [128][128] dup'd z: (z,z) pairs
#define F_CB0   (128 * 128)              // [128][128] c tile buf 0 (k-major)
#define F_CB1   (F_CB0 + 128 * 128)      // buf 1
#define F_RS    (F_CB1 + 128 * 128)      // [64] ||z||^2
#define SMEM_BYTES ((F_RS + 64) * 4)     // 196864 B -> 1 CTA/SM, 512 thr

typedef unsigned long long u64;

__device__ float g_cbT[DDIM * KCODES];   // transposed codebook [d][k]
__device__ float g_snorm[KCODES];
__device__ int   g_idx[NVEC];

__device__ __forceinline__ uint32_t smem_u32(const void* p) {
    uint32_t a;
    asm("{ .reg .u64 t; cvta.to.shared.u64 t, %1; cvt.u32.u64 %0, t; }"
        : "=r"(a) : "l"(p));
    return a;
}
__device__ __forceinline__ void cpasync16(uint32_t s, const void* g) {
    asm volatile("cp.async.cg.shared.global [%0], [%1], 16;" :: "r"(s), "l"(g));
}

// ||c_k||^2: strictly sequential i=0..127 fp32 mul+add (bit-identical to ref).
__global__ void snorm_kernel(const float* __restrict__ cb) {
    int k = blockIdx.x * blockDim.x + threadIdx.x;
    if (k >= KCODES) return;
    const float4* row = (const float4*)(cb + k * DDIM);
    float s = 0.f;
#pragma unroll
    for (int i = 0; i < 32; i++) {
        float4 v = row[i];
        s = __fadd_rn(s, __fmul_rn(v.x, v.x));
        s = __fadd_rn(s, __fmul_rn(v.y, v.y));
        s = __fadd_rn(s, __fmul_rn(v.z, v.z));
        s = __fadd_rn(s, __fmul_rn(v.w, v.w));
    }
    g_snorm[k] = s;
}

// Codebook transpose -> g_cbT[d][k] (enables contiguous cp.async tile fills).
__global__ void transpose_kernel(const float* __restrict__ cb) {
    int idx = blockIdx.x * blockDim.x + threadIdx.x;   // 128 * 256
    int d = idx >> 8, kg = idx & 255;
    float4 v;
    v.x = cb[(4 * kg + 0) * DDIM + d];
    v.y = cb[(4 * kg + 1) * DDIM + d];
    v.z = cb[(4 * kg + 2) * DDIM + d];
    v.w = cb[(4 * kg + 3) * DDIM + d];
    *(float4*)(g_cbT + d * KCODES + 4 * kg) = v;
}

// argmin: FFMA2 GEMM, dup'd-z smem (zero dup instructions), cp.async
// double-buffered code tiles. dist = fl( fl(r + s_k) - 2*p_k ), lowest-index
// tie-break — bit-identical to the proven arithmetic.
__global__ void __launch_bounds__(NT, 1)
argmin_kernel(const float* __restrict__ z) {
    extern __shared__ float smem[];
    float* zs2 = smem + F_ZS2;
    float* rs  = smem + F_RS;
    const uint32_t cb_s[2] = { smem_u32(smem + F_CB0), smem_u32(smem + F_CB1) };

    const int tid = threadIdx.x, wid = tid >> 5, tk = tid & 31;
    const int nbase = blockIdx.x * BN;
    const float* zb = z + (size_t)(nbase >> 12) * (DDIM * 4096) + (nbase & 4095);

    // z tile with duplication: zs2[d][2n] = zs2[d][2n+1] = z[d][n].
    for (int e = tid; e < DDIM * BN; e += NT) {
        int d = e >> 6, n = e & 63;
        float v = zb[(size_t)d * 4096 + n];
        *(float2*)(zs2 + d * 128 + 2 * n) = make_float2(v, v);
    }
    __syncthreads();

    // r_n: sequential fp32 sum of squares, d = 0..127 in order.
    if (tid < BN) {
        float r = 0.f;
#pragma unroll
        for (int d = 0; d < DDIM; d++) {
            float v = zs2[d * 128 + 2 * tid];
            r = __fadd_rn(r, __fmul_rn(v, v));
        }
        rs[tid] = r;
    }

    // Prologue: cp.async fill of chunk 0 into buf 0.
    {
        const float* g0 = g_cbT;
#pragma unroll
        for (int s = 0; s < 8; s++) {
            int seg = tid + s * NT;            // 4096 16B segments
            int d = seg >> 5, o = seg & 31;
            cpasync16(cb_s[0] + (d * 128 + o * 4) * 4, g0 + d * KCODES + o * 4);
        }
        asm volatile("cp.async.commit_group;");
    }
    __syncthreads();

    float rreg[4];
#pragma unroll
    for (int i = 0; i < 4; i++) rreg[i] = rs[4 * wid + i];

    float best[4];
    int   bidx[4];
#pragma unroll
    for (int i = 0; i < 4; i++) { best[i] = 3.4e38f; bidx[i] = 0; }

    for (int ch = 0; ch < NCHUNK; ch++) {
        const uint32_t cur = cb_s[ch & 1];
        // Issue next chunk's fill into the other buffer (protected by bar B).
        if (ch + 1 < NCHUNK) {
            const float* gn = g_cbT + (ch + 1) * BKC;
#pragma unroll
            for (int s = 0; s < 8; s++) {
                int seg = tid + s * NT;
                int d = seg >> 5, o = seg & 31;
                cpasync16(cb_s[(ch + 1) & 1] + (d * 128 + o * 4) * 4,
                          gn + d * KCODES + o * 4);
            }
            asm volatile("cp.async.commit_group;");
            asm volatile("cp.async.wait_group 1;");
        } else {
            asm volatile("cp.async.wait_group 0;");
        }
        __syncthreads();   // bar A: chunk ch data visible to all

        // acc[v*2+p]: lanes = codes (4tk+2p, 4tk+2p+1) for vector 4*wid+v.
        u64 acc[8];
#pragma unroll
        for (int a = 0; a < 8; a++) acc[a] = 0ull;

#pragma unroll 4
        for (int d = 0; d < DDIM; d++) {
            // dup'd z: LDS.128 broadcast -> 2 dup-pairs each, no mov needed.
            float4 zA = *(const float4*)(zs2 + d * 128 + wid * 8);
            float4 zB = *(const float4*)(zs2 + d * 128 + wid * 8 + 4);
            // codes: LDS.128, 4 adjacent codes (conflict-free, 4*tk words).
            float4 c4;
            asm volatile("ld.shared.v4.f32 {%0,%1,%2,%3}, [%4];"
                         : "=f"(c4.x), "=f"(c4.y), "=f"(c4.z), "=f"(c4.w)
                         : "r"(cur + d * 128 * 4 + tk * 16));
            u64 zd[4], cp[2];
            zd[0] = *(const u64*)&zA.x;   // (z0,z0)
            zd[1] = *(const u64*)&zA.z;   // (z1,z1)
            zd[2] = *(const u64*)&zB.x;   // (z2,z2)
            zd[3] = *(const u64*)&zB.z;   // (z3,z3)
            cp[0] = *(const u64*)&c4.x;   // (c0,c1)
            cp[1] = *(const u64*)&c4.z;   // (c2,c3)
#pragma unroll
            for (int v = 0; v < 4; v++)
#pragma unroll
                for (int p = 0; p < 2; p++)
                    asm("fma.rn.f32x2 %0, %1, %2, %0;"
                        : "+l"(acc[v * 2 + p]) : "l"(zd[v]), "l"(cp[p]));
        }
        __syncthreads();   // bar B: all reads of cur done before it is refilled

        // Epilogue: dist = fl( fl(r+s) - 2p ); k ascending per lane.
        const int kb = ch * BKC + 4 * tk;
        const float4 sv = *(const float4*)(g_snorm + kb);
        const float s4[4] = { sv.x, sv.y, sv.z, sv.w };
#pragma unroll
        for (int v = 0; v < 4; v++) {
#pragma unroll
            for (int p = 0; p < 2; p++) {
                u64 ap = acc[v * 2 + p];
                float plo = __uint_as_float((unsigned)(ap & 0xffffffffu));
                float phi = __uint_as_float((unsigned)(ap >> 32));
                float dlo = __fmaf_rn(-2.f, plo, __fadd_rn(rreg[v], s4[2 * p]));
                float dhi = __fmaf_rn(-2.f, phi, __fadd_rn(rreg[v], s4[2 * p + 1]));
                int klo = kb + 2 * p, khi = klo + 1;
                if (dlo < best[v] || (dlo == best[v] && klo < bidx[v])) {
                    best[v] = dlo; bidx[v] = klo;
                }
                if (dhi < best[v] || (dhi == best[v] && khi < bidx[v])) {
                    best[v] = dhi; bidx[v] = khi;
                }
            }
        }
    }

    // Cross-lane argmin, lowest-index tie-break (order-independent combine).
#pragma unroll
    for (int v = 0; v < 4; v++) {
        float val = best[v]; int id = bidx[v];
#pragma unroll
        for (int off = 16; off > 0; off >>= 1) {
            float v2 = __shfl_down_sync(0xffffffffu, val, off);
            int   i2 = __shfl_down_sync(0xffffffffu, id, off);
            if (v2 < val || (v2 == val && i2 < id)) { val = v2; id = i2; }
        }
        if (tk == 0) g_idx[nbase + 4 * wid + v] = id;
    }
}

// Gather: float4 codebook reads, fully-coalesced writes.
__global__ void gather_kernel(const float* __restrict__ cb, float* __restrict__ out) {
    int t = blockIdx.x * blockDim.x + threadIdx.x;   // t < NVEC*32
    int hw = t & 4095;
    int i4 = (t >> 12) & 31;
    int b  = t >> 17;
    int n  = (b << 12) | hw;
    float4 v = *(const float4*)(cb + g_idx[n] * DDIM + i4 * 4);
    size_t o = ((size_t)b << 19) | ((size_t)(i4 * 4) << 12) | (size_t)hw;
    out[o]         = v.x;
    out[o + 4096]  = v.y;
    out[o + 8192]  = v.z;
    out[o + 12288] = v.w;
}

extern "C" void kernel_launch(void* const* d_in, const int* in_sizes, int n_in,
                              void* d_out, int out_size) {
    const float* z  = (const float*)d_in[0];
    const float* cb = (const float*)d_in[1];
    float* out = (float*)d_out;

    cudaFuncSetAttribute(argmin_kernel,
                         cudaFuncAttributeMaxDynamicSharedMemorySize, SMEM_BYTES);

    snorm_kernel<<<(KCODES + 255) / 256, 256>>>(cb);
    transpose_kernel<<<DDIM * 256 / 256, 256>>>(cb);
    argmin_kernel<<<NVEC / BN, NT, SMEM_BYTES>>>(z);
    gather_kernel<<<(NVEC * 32) / 256, 256>>>(cb, out);
}

// round 12
// speedup vs baseline: 1.2421x; 1.2421x over previous
#include <cuda_runtime.h>
#include <cstdint>

#define NVEC     131072      // 32 * 64 * 64 vectors
#define DDIM     128
#define KCODES   1024
#define BN       64          // vectors per block
#define BKC      64          // codes per chunk
#define CSTR     65          // padded row stride for code tile (conflict-free)
#define NTHREADS 256

// zs 32768B + cs 33280B + rs/ids 256B = 66304B -> 3 CTAs/SM
#define SMEM_BYTES ((DDIM * BN + DDIM * CSTR + BN) * 4)

typedef unsigned long long u64;

__device__ float g_snorm[KCODES];

// ||c_k||^2: strictly sequential i=0..127 fp32 mul+add (bit-identical to ref).
// 32 blocks x 32 threads -> 32 SMs busy instead of 4.
__global__ void snorm_kernel(const float* __restrict__ cb) {
    int k = blockIdx.x * 32 + threadIdx.x;
    const float4* row = (const float4*)(cb + k * DDIM);
    float4 v[32];
#pragma unroll
    for (int i = 0; i < 32; i++) v[i] = row[i];
    float s = 0.f;
#pragma unroll
    for (int i = 0; i < 32; i++) {
        s = __fadd_rn(s, __fmul_rn(v[i].x, v[i].x));
        s = __fadd_rn(s, __fmul_rn(v[i].y, v[i].y));
        s = __fadd_rn(s, __fmul_rn(v[i].z, v[i].z));
        s = __fadd_rn(s, __fmul_rn(v[i].w, v[i].w));
    }
    g_snorm[k] = s;
}

// argmin + fused gather. dist = fl( fl(r + s_k) - 2*p_k ), lowest-index
// tie-break; per-lane code visit order identical to the proven R10 kernel.
__global__ void __launch_bounds__(NTHREADS, 3)
argmin_kernel(const float* __restrict__ z, const float* __restrict__ cb,
              float* __restrict__ out) {
    extern __shared__ float smem[];
    float* zs = smem;                 // [128][64]  z tile, transposed (d-major)
    float* cs = smem + DDIM * BN;     // [128][65]  code tile, padded
    float* rs = cs + DDIM * CSTR;     // [64]       ||z||^2 / later: ids
    int*   ids = (int*)rs;

    const int nbase = blockIdx.x * BN;
    const int b  = nbase >> 12;          // n = b*4096 + h*64 + w
    const int hw = nbase & 4095;
    const float* zb = z + (size_t)b * (DDIM * 4096) + hw;

    // Load z tile: global coalesced over hw, smem write conflict-free.
    for (int t = threadIdx.x; t < DDIM * BN; t += NTHREADS) {
        int i = t >> 6, nl = t & (BN - 1);
        zs[i * BN + nl] = zb[(size_t)i * 4096 + nl];
    }
    __syncthreads();

    // r_n = sequential fp32 sum of squares over d (i = 0..127 in order).
    if (threadIdx.x < BN) {
        float r = 0.f;
#pragma unroll
        for (int i = 0; i < DDIM; i++) {
            float v = zs[i * BN + threadIdx.x];
            r = __fadd_rn(r, __fmul_rn(v, v));
        }
        rs[threadIdx.x] = r;
    }
    __syncthreads();

    const int tn = threadIdx.x >> 5;   // warp id: owns vectors tn*8..tn*8+7
    const int tk = threadIdx.x & 31;   // lane: owns codes tk + 32*j, j<2

    float rreg[8];
#pragma unroll
    for (int n = 0; n < 8; n++) rreg[n] = rs[tn * 8 + n];

    float best[8];
    int   bidx[8];
#pragma unroll
    for (int n = 0; n < 8; n++) { best[n] = 3.4e38f; bidx[n] = 0; }

    for (int chunk = 0; chunk < KCODES / BKC; chunk++) {
        const int kbase = chunk * BKC;
        __syncthreads();
        // Fill code tile transposed: gmem coalesced over i, stride-65 writes
        // (bank = (65*i + kl) mod 32 -> distinct per warp phase).
        for (int t = threadIdx.x; t < BKC * DDIM; t += NTHREADS) {
            int kl = t >> 7, i = t & (DDIM - 1);
            cs[i * CSTR + kl] = cb[(kbase + kl) * DDIM + i];
        }
        __syncthreads();

        // accp[n2*2+j]: lo = acc[2*n2][j], hi = acc[2*n2+1][j]
        u64 accp[8];
#pragma unroll
        for (int a = 0; a < 8; a++) accp[a] = 0ull;

#pragma unroll 4
        for (int d = 0; d < DDIM; d++) {
            const float* zrow = zs + d * BN + tn * 8;
            u64 zp[4];
#pragma unroll
            for (int n2 = 0; n2 < 4; n2++)
                zp[n2] = *(const u64*)(zrow + 2 * n2);   // (z[2n2], z[2n2+1])
            const float* crow = cs + d * CSTR + tk;
#pragma unroll
            for (int j = 0; j < 2; j++) {
                float c = crow[j * 32];
                u64 cd;
                asm("mov.b64 %0, {%1, %1};" : "=l"(cd) : "f"(c));
#pragma unroll
                for (int n2 = 0; n2 < 4; n2++)
                    asm("fma.rn.f32x2 %0, %1, %2, %0;"
                        : "+l"(accp[n2 * 2 + j]) : "l"(zp[n2]), "l"(cd));
            }
        }

        // dist = fl( fl(r + s_k) - 2*p ): 2*p exact in fp32, so the fused
        // FMA's single rounding equals the reference's separate subtract.
        // k ascending per lane (chunk asc, j asc) — same order as R10.
#pragma unroll
        for (int j = 0; j < 2; j++) {
            const int k = kbase + tk + j * 32;
            const float s = g_snorm[k];
#pragma unroll
            for (int n2 = 0; n2 < 4; n2++) {
                u64 ap = accp[n2 * 2 + j];
                float plo = __uint_as_float((unsigned)(ap & 0xffffffffu));
                float phi = __uint_as_float((unsigned)(ap >> 32));
                int nlo = 2 * n2, nhi = 2 * n2 + 1;
                float dlo = __fmaf_rn(-2.f, plo, __fadd_rn(rreg[nlo], s));
                float dhi = __fmaf_rn(-2.f, phi, __fadd_rn(rreg[nhi], s));
                if (dlo < best[nlo] || (dlo == best[nlo] && k < bidx[nlo])) {
                    best[nlo] = dlo; bidx[nlo] = k;
                }
                if (dhi < best[nhi] || (dhi == best[nhi] && k < bidx[nhi])) {
                    best[nhi] = dhi; bidx[nhi] = k;
                }
            }
        }
    }

    // Cross-lane argmin per vector, lowest-index tie-break.
#pragma unroll
    for (int n = 0; n < 8; n++) {
        float v = best[n]; int id = bidx[n];
#pragma unroll
        for (int off = 16; off > 0; off >>= 1) {
            float v2 = __shfl_down_sync(0xffffffffu, v, off);
            int   i2 = __shfl_down_sync(0xffffffffu, id, off);
            if (v2 < v || (v2 == v && i2 < id)) { v = v2; id = i2; }
        }
        if (tk == 0) ids[tn * 8 + n] = id;
    }
    __syncthreads();

    // Fused gather: out[b, i, hw+v] = cb[ids[v], i]; 128B-coalesced stores,
    // codebook reads are L2-resident; hides under other CTAs' FMA streams.
    float* ob = out + (size_t)b * (DDIM * 4096) + hw;
    for (int t = threadIdx.x; t < DDIM * BN; t += NTHREADS) {
        int i = t >> 6, v = t & (BN - 1);
        ob[(size_t)i * 4096 + v] = cb[ids[v] * DDIM + i];
    }
}

extern "C" void kernel_launch(void* const* d_in, const int* in_sizes, int n_in,
                              void* d_out, int out_size) {
    const float* z  = (const float*)d_in[0];
    const float* cb = (const float*)d_in[1];
    float* out = (float*)d_out;

    cudaFuncSetAttribute(argmin_kernel,
                         cudaFuncAttributeMaxDynamicSharedMemorySize, SMEM_BYTES);

    snorm_kernel<<<32, 32>>>(cb);
    argmin_kernel<<<NVEC / BN, NTHREADS, SMEM_BYTES>>>(z, cb, out);
}

// round 13
// speedup vs baseline: 1.5113x; 1.2167x over previous
#include <cuda_runtime.h>
#include <cstdint>

#define NVEC    131072
#define DDIM    128
#define KCODES  1024
#define BN      64           // vectors per CTA
#define BKC     128          // codes per chunk
#define NCHUNK  (KCODES / BKC)
#define NT      128

// smem floats: zs[128*64] + cs[128*128] + ss[1024] + rs[64] = 25664 -> 102656 B
#define F_ZS 0
#define F_CS (DDIM * BN)
#define F_SS (F_CS + DDIM * BKC)
#define F_RS (F_SS + KCODES)
#define SMEM_BYTES ((F_RS + BN) * 4)

typedef unsigned long long u64;

__device__ float g_cbT[DDIM * KCODES];   // transposed codebook [d][k]
__device__ float g_snorm[KCODES];

// ||c_k||^2: strictly sequential i=0..127 fp32 mul+add (bit-identical to ref).
__global__ void snorm_kernel(const float* __restrict__ cb) {
    int k = blockIdx.x * 32 + threadIdx.x;
    const float4* row = (const float4*)(cb + k * DDIM);
    float4 v[32];
#pragma unroll
    for (int i = 0; i < 32; i++) v[i] = row[i];
    float s = 0.f;
#pragma unroll
    for (int i = 0; i < 32; i++) {
        s = __fadd_rn(s, __fmul_rn(v[i].x, v[i].x));
        s = __fadd_rn(s, __fmul_rn(v[i].y, v[i].y));
        s = __fadd_rn(s, __fmul_rn(v[i].z, v[i].z));
        s = __fadd_rn(s, __fmul_rn(v[i].w, v[i].w));
    }
    g_snorm[k] = s;
}

// Codebook transpose -> g_cbT[d][k] (makes chunk fills pure LDG.128/STS.128).
__global__ void transpose_kernel(const float* __restrict__ cb) {
    int idx = blockIdx.x * blockDim.x + threadIdx.x;   // 128 * 256
    int d = idx >> 8, kg = idx & 255;
    float4 v;
    v.x = cb[(4 * kg + 0) * DDIM + d];
    v.y = cb[(4 * kg + 1) * DDIM + d];
    v.z = cb[(4 * kg + 2) * DDIM + d];
    v.w = cb[(4 * kg + 3) * DDIM + d];
    *(float4*)(g_cbT + d * KCODES + 4 * kg) = v;
}

// argmin + fused gather. 8 vectors x 8 codes per thread (2 B smem / FFMA2,
// FMA-bound by design). dist = fl( fl(r + s_k) - 2*p_k ), lowest-index
// tie-break; per-lane k order ascending -> bit-identical tie semantics.
__global__ void __launch_bounds__(NT, 2)
argmin_kernel(const float* __restrict__ z, const float* __restrict__ cb,
              float* __restrict__ out) {
    extern __shared__ float smem[];
    float* zs = smem + F_ZS;     // [128][64]  z tile, d-major, unpadded
    float* cs = smem + F_CS;     // [128][128] code tile, k-major, unpadded
    float* ss = smem + F_SS;     // [1024]     snorm
    float* rs = smem + F_RS;     // [64]       ||z||^2 / later ids
    int*   ids = (int*)rs;

    const int tid = threadIdx.x;
    const int wid = tid >> 5, lane = tid & 31;
    const int h = lane >> 4, l = lane & 15;
    const int g = wid * 2 + h;             // vector group: vectors 8g..8g+7

    const int nbase = blockIdx.x * BN;
    const int b  = nbase >> 12;
    const int hw = nbase & 4095;
    const float* zb = z + (size_t)b * (DDIM * 4096) + hw;

    // Fill zs: float4 gmem loads (coalesced over hw), float4 smem stores.
#pragma unroll
    for (int i = 0; i < 16; i++) {
        int idx = tid + i * NT;            // 2048 float4s
        int d = idx >> 4, v4 = idx & 15;
        *(float4*)(zs + d * BN + v4 * 4) =
            *(const float4*)(zb + (size_t)d * 4096 + v4 * 4);
    }
    // Stage snorm into smem (once).
#pragma unroll
    for (int i = 0; i < 2; i++) {
        int idx = tid + i * NT;            // 256 float4s
        *(float4*)(ss + idx * 4) = *(const float4*)(g_snorm + idx * 4);
    }
    __syncthreads();

    // r_n = sequential fp32 sum of squares over d = 0..127 in order.
    if (tid < BN) {
        float r = 0.f;
#pragma unroll
        for (int d = 0; d < DDIM; d++) {
            float v = zs[d * BN + tid];
            r = __fadd_rn(r, __fmul_rn(v, v));
        }
        rs[tid] = r;
    }
    __syncthreads();

    float rreg[8];
#pragma unroll
    for (int n = 0; n < 8; n++) rreg[n] = rs[8 * g + n];

    float best[8];
    int   bidx[8];
#pragma unroll
    for (int n = 0; n < 8; n++) { best[n] = 3.4e38f; bidx[n] = 0; }

    for (int ch = 0; ch < NCHUNK; ch++) {
        __syncthreads();
        // Fill cs from transposed codebook: LDG.128 + STS.128, both coalesced.
        const float* gsrc = g_cbT + ch * BKC;
#pragma unroll
        for (int i = 0; i < 32; i++) {
            int idx = tid + i * NT;        // 4096 float4s
            int d = idx >> 5, k4 = idx & 31;
            *(float4*)(cs + d * BKC + k4 * 4) =
                *(const float4*)(gsrc + d * KCODES + k4 * 4);
        }
        __syncthreads();

        // acc[n2*8+j]: lo = acc vector 2n2, hi = vector 2n2+1, code l+16j.
        u64 acc[32];
#pragma unroll
        for (int a = 0; a < 32; a++) acc[a] = 0ull;

#pragma unroll 4
        for (int d = 0; d < DDIM; d++) {
            const float* zrow = zs + d * BN + 8 * g;   // 2 addrs/warp: broadcast
            u64 zp[4];
#pragma unroll
            for (int n2 = 0; n2 < 4; n2++)
                zp[n2] = *(const u64*)(zrow + 2 * n2);  // (z[2n2], z[2n2+1])
            const float* crow = cs + d * BKC + l;       // 16 banks + 2-way bcast
#pragma unroll
            for (int j = 0; j < 8; j++) {
                float c = crow[16 * j];
                u64 cd;
                asm("mov.b64 %0, {%1, %1};" : "=l"(cd) : "f"(c));
#pragma unroll
                for (int n2 = 0; n2 < 4; n2++)
                    asm("fma.rn.f32x2 %0, %1, %2, %0;"
                        : "+l"(acc[n2 * 8 + j]) : "l"(zp[n2]), "l"(cd));
            }
        }

        // dist = fl( fl(r + s_k) - 2*p ); k ascending per lane (j asc, ch asc).
#pragma unroll
        for (int j = 0; j < 8; j++) {
            const int k = ch * BKC + l + 16 * j;
            const float s = ss[k];
#pragma unroll
            for (int n2 = 0; n2 < 4; n2++) {
                u64 ap = acc[n2 * 8 + j];
                float plo = __uint_as_float((unsigned)(ap & 0xffffffffu));
                float phi = __uint_as_float((unsigned)(ap >> 32));
                int nlo = 2 * n2, nhi = 2 * n2 + 1;
                float dlo = __fmaf_rn(-2.f, plo, __fadd_rn(rreg[nlo], s));
                float dhi = __fmaf_rn(-2.f, phi, __fadd_rn(rreg[nhi], s));
                if (dlo < best[nlo] || (dlo == best[nlo] && k < bidx[nlo])) {
                    best[nlo] = dlo; bidx[nlo] = k;
                }
                if (dhi < best[nhi] || (dhi == best[nhi] && k < bidx[nhi])) {
                    best[nhi] = dhi; bidx[nhi] = k;
                }
            }
        }
    }

    // Reduce across the 16 lanes (l=0..15) of each half-warp; offsets <= 8
    // keep the tree inside each half. Lowest-index tie-break.
#pragma unroll
    for (int n = 0; n < 8; n++) {
        float v = best[n]; int id = bidx[n];
#pragma unroll
        for (int off = 8; off > 0; off >>= 1) {
            float v2 = __shfl_down_sync(0xffffffffu, v, off);
            int   i2 = __shfl_down_sync(0xffffffffu, id, off);
            if (v2 < v || (v2 == v && i2 < id)) { v = v2; id = i2; }
        }
        if (l == 0) ids[8 * g + n] = id;
    }
    __syncthreads();

    // Fused gather: out[b, i, hw+v] = cb[ids[v], i]; coalesced stores,
    // codebook reads L2-resident; hides under the co-resident CTA's FMA.
    float* ob = out + (size_t)b * (DDIM * 4096) + hw;
    for (int t = tid; t < DDIM * BN; t += NT) {
        int i = t >> 6, v = t & (BN - 1);
        ob[(size_t)i * 4096 + v] = cb[ids[v] * DDIM + i];
    }
}

extern "C" void kernel_launch(void* const* d_in, const int* in_sizes, int n_in,
                              void* d_out, int out_size) {
    const float* z  = (const float*)d_in[0];
    const float* cb = (const float*)d_in[1];
    float* out = (float*)d_out;

    cudaFuncSetAttribute(argmin_kernel,
                         cudaFuncAttributeMaxDynamicSharedMemorySize, SMEM_BYTES);

    snorm_kernel<<<32, 32>>>(cb);
    transpose_kernel<<<DDIM * 256 / 256, 256>>>(cb);
    argmin_kernel<<<NVEC / BN, NT, SMEM_BYTES>>>(z, cb, out);
}

// round 14
// speedup vs baseline: 1.5371x; 1.0171x over previous
#include <cuda_runtime.h>
#include <cstdint>

#define NVEC    131072
#define DDIM    128
#define KCODES  1024
#define BN      128          // vectors per CTA
#define BKC     64           // codes per chunk
#define NCHUNK  (KCODES / BKC)
#define NT      128

// smem floats: zs[128*128] + cs[128*64] + ss[1024] + rs[128] -> 103040 B
#define F_ZS 0
#define F_CS (DDIM * BN)
#define F_SS (F_CS + DDIM * BKC)
#define F_RS (F_SS + KCODES)
#define SMEM_BYTES ((F_RS + BN) * 4)

typedef unsigned long long u64;

__device__ float g_cbT[DDIM * KCODES];   // transposed codebook [d][k]
__device__ float g_snorm[KCODES];

// ||c_k||^2: strictly sequential i=0..127 fp32 mul+add (bit-identical to ref).
__global__ void snorm_kernel(const float* __restrict__ cb) {
    int k = blockIdx.x * 32 + threadIdx.x;
    const float4* row = (const float4*)(cb + k * DDIM);
    float4 v[32];
#pragma unroll
    for (int i = 0; i < 32; i++) v[i] = row[i];
    float s = 0.f;
#pragma unroll
    for (int i = 0; i < 32; i++) {
        s = __fadd_rn(s, __fmul_rn(v[i].x, v[i].x));
        s = __fadd_rn(s, __fmul_rn(v[i].y, v[i].y));
        s = __fadd_rn(s, __fmul_rn(v[i].z, v[i].z));
        s = __fadd_rn(s, __fmul_rn(v[i].w, v[i].w));
    }
    g_snorm[k] = s;
}

// Codebook transpose -> g_cbT[d][k] (chunk fills become LDG.128/STS.128).
__global__ void transpose_kernel(const float* __restrict__ cb) {
    int idx = blockIdx.x * blockDim.x + threadIdx.x;   // 128 * 256
    int d = idx >> 8, kg = idx & 255;
    float4 v;
    v.x = cb[(4 * kg + 0) * DDIM + d];
    v.y = cb[(4 * kg + 1) * DDIM + d];
    v.z = cb[(4 * kg + 2) * DDIM + d];
    v.w = cb[(4 * kg + 3) * DDIM + d];
    *(float4*)(g_cbT + d * KCODES + 4 * kg) = v;
}

// argmin + fused gather. 8 vectors x 8 codes per thread, BN=128 halves the
// per-chip L2 fill traffic vs BN=64. dist = fl( fl(r + s_k) - 2*p_k ),
// lowest-index tie-break; per-lane k order ascending (bit-identical ties).
__global__ void __launch_bounds__(NT, 2)
argmin_kernel(const float* __restrict__ z, const float* __restrict__ cb,
              float* __restrict__ out) {
    extern __shared__ float smem[];
    float* zs = smem + F_ZS;     // [128][128] z tile, d-major
    float* cs = smem + F_CS;     // [128][64]  code tile, k-major
    float* ss = smem + F_SS;     // [1024]     snorm
    float* rs = smem + F_RS;     // [128]      ||z||^2 / later ids
    int*   ids = (int*)rs;

    const int tid = threadIdx.x;
    const int wid = tid >> 5, lane = tid & 31;
    const int vg = wid * 4 + (lane >> 3);  // vector group 0..15: vectors 8vg..8vg+7
    const int cg = lane & 7;               // code lane: codes cg + 8j, j<8

    const int nbase = blockIdx.x * BN;
    const int b  = nbase >> 12;
    const int hw = nbase & 4095;
    const float* zb = z + (size_t)b * (DDIM * 4096) + hw;

    // Fill zs: float4 gmem loads (coalesced over hw), float4 smem stores.
#pragma unroll
    for (int i = 0; i < 32; i++) {
        int idx = tid + i * NT;            // 4096 float4s
        int d = idx >> 5, v4 = idx & 31;
        *(float4*)(zs + d * BN + v4 * 4) =
            *(const float4*)(zb + (size_t)d * 4096 + v4 * 4);
    }
    // Stage snorm into smem (once).
#pragma unroll
    for (int i = 0; i < 2; i++) {
        int idx = tid + i * NT;            // 256 float4s
        *(float4*)(ss + idx * 4) = *(const float4*)(g_snorm + idx * 4);
    }
    __syncthreads();

    // r_n = sequential fp32 sum of squares over d = 0..127 in order.
    {
        float r = 0.f;
#pragma unroll
        for (int d = 0; d < DDIM; d++) {
            float v = zs[d * BN + tid];
            r = __fadd_rn(r, __fmul_rn(v, v));
        }
        rs[tid] = r;
    }
    __syncthreads();

    float rreg[8];
#pragma unroll
    for (int n = 0; n < 8; n++) rreg[n] = rs[8 * vg + n];

    float best[8];
    int   bidx[8];
#pragma unroll
    for (int n = 0; n < 8; n++) { best[n] = 3.4e38f; bidx[n] = 0; }

    for (int ch = 0; ch < NCHUNK; ch++) {
        __syncthreads();
        // Fill cs: contiguous 64-float rows of g_cbT (LDG.128 + STS.128).
        const float* gsrc = g_cbT + ch * BKC;
#pragma unroll
        for (int i = 0; i < 16; i++) {
            int idx = tid + i * NT;        // 2048 float4s
            int d = idx >> 4, k4 = idx & 15;
            *(float4*)(cs + d * BKC + k4 * 4) =
                *(const float4*)(gsrc + d * KCODES + k4 * 4);
        }
        __syncthreads();

        // acc[n2*8+j]: lo = vector 8vg+2n2, hi = 8vg+2n2+1, code cg+8j.
        u64 acc[32];
#pragma unroll
        for (int a = 0; a < 32; a++) acc[a] = 0ull;

#pragma unroll 4
        for (int d = 0; d < DDIM; d++) {
            const float* zrow = zs + d * BN + 8 * vg;  // 4 addrs/warp: broadcast
            u64 zp[4];
#pragma unroll
            for (int n2 = 0; n2 < 4; n2++)
                zp[n2] = *(const u64*)(zrow + 2 * n2);  // (z[2n2], z[2n2+1])
            const float* crow = cs + d * BKC + cg;      // 8 banks, 4-way bcast
#pragma unroll
            for (int j = 0; j < 8; j++) {
                float c = crow[8 * j];
                u64 cd;
                asm("mov.b64 %0, {%1, %1};" : "=l"(cd) : "f"(c));
#pragma unroll
                for (int n2 = 0; n2 < 4; n2++)
                    asm("fma.rn.f32x2 %0, %1, %2, %0;"
                        : "+l"(acc[n2 * 8 + j]) : "l"(zp[n2]), "l"(cd));
            }
        }

        // dist = fl( fl(r + s_k) - 2*p ); k ascending per lane (j asc, ch asc).
#pragma unroll
        for (int j = 0; j < 8; j++) {
            const int k = ch * BKC + cg + 8 * j;
            const float s = ss[k];
#pragma unroll
            for (int n2 = 0; n2 < 4; n2++) {
                u64 ap = acc[n2 * 8 + j];
                float plo = __uint_as_float((unsigned)(ap & 0xffffffffu));
                float phi = __uint_as_float((unsigned)(ap >> 32));
                int nlo = 2 * n2, nhi = 2 * n2 + 1;
                float dlo = __fmaf_rn(-2.f, plo, __fadd_rn(rreg[nlo], s));
                float dhi = __fmaf_rn(-2.f, phi, __fadd_rn(rreg[nhi], s));
                if (dlo < best[nlo] || (dlo == best[nlo] && k < bidx[nlo])) {
                    best[nlo] = dlo; bidx[nlo] = k;
                }
                if (dhi < best[nhi] || (dhi == best[nhi] && k < bidx[nhi])) {
                    best[nhi] = dhi; bidx[nhi] = k;
                }
            }
        }
    }

    // Reduce across the 8 lanes (cg = 0..7) sharing each vector group.
#pragma unroll
    for (int n = 0; n < 8; n++) {
        float v = best[n]; int id = bidx[n];
#pragma unroll
        for (int off = 4; off > 0; off >>= 1) {
            float v2 = __shfl_down_sync(0xffffffffu, v, off);
            int   i2 = __shfl_down_sync(0xffffffffu, id, off);
            if (v2 < v || (v2 == v && i2 < id)) { v = v2; id = i2; }
        }
        if (cg == 0) ids[8 * vg + n] = id;
    }
    __syncthreads();

    // Fused gather: out[b, i, hw+v] = cb[ids[v], i]; coalesced stores,
    // codebook reads L2-resident; hides under the co-resident CTA's FMA.
    float* ob = out + (size_t)b * (DDIM * 4096) + hw;
#pragma unroll
    for (int i = 0; i < DDIM; i++)
        ob[(size_t)i * 4096 + tid] = cb[ids[tid] * DDIM + i];
}

extern "C" void kernel_launch(void* const* d_in, const int* in_sizes, int n_in,
                              void* d_out, int out_size) {
    const float* z  = (const float*)d_in[0];
    const float* cb = (const float*)d_in[1];
    float* out = (float*)d_out;

    cudaFuncSetAttribute(argmin_kernel,
                         cudaFuncAttributeMaxDynamicSharedMemorySize, SMEM_BYTES);

    snorm_kernel<<<32, 32>>>(cb);
    transpose_kernel<<<DDIM * 256 / 256, 256>>>(cb);
    argmin_kernel<<<NVEC / BN, NT, SMEM_BYTES>>>(z, cb, out);
}